// round 3
// baseline (speedup 1.0000x reference)
#include <cuda_runtime.h>
#include <math.h>

#define BB  2
#define TT  2048
#define CCH 1024
#define HH  16
#define HSZ 64

// Scratch (alloc-free rule: __device__ globals). 16 MB each + 16 MB O = 64 MB.
__device__ float g_K[BB * HH * TT * HSZ];
__device__ float g_Q[BB * HH * TT * HSZ];
__device__ float g_V[BB * HH * TT * HSZ];
__device__ float g_O[BB * TT * CCH];

__device__ __forceinline__ unsigned f2tf32(float f) {
    unsigned u;
    asm("cvt.rna.tf32.f32 %0, %1;" : "=r"(u) : "f"(f));
    return u;
}

__device__ __forceinline__ void mma8(float* c, const unsigned* a, const unsigned* b) {
    asm volatile(
        "mma.sync.aligned.m16n8k8.row.col.f32.tf32.tf32.f32 "
        "{%0,%1,%2,%3}, {%4,%5,%6,%7}, {%8,%9}, {%0,%1,%2,%3};\n"
        : "+f"(c[0]), "+f"(c[1]), "+f"(c[2]), "+f"(c[3])
        : "r"(a[0]), "r"(a[1]), "r"(a[2]), "r"(a[3]), "r"(b[0]), "r"(b[1]));
}

// ---------------------------------------------------------------------------
// Generic TF32 GEMM: C[M,N] = A[M,K] @ B[K,N], all row-major.
// IN_O:    1 -> A is ignored, read from g_O.
// OUT_QKV: 1 -> scatter columns [0,C)->g_K, [C,2C)->g_Q, [2C,3C)->g_V in
//               [b,h,t,hs] layout (module order of the reference: K, Q, V).
// Block 256 threads (8 warps, 2x4), tile 128x128, BK=32.
// ---------------------------------------------------------------------------
template <int IN_O, int OUT_QKV>
__global__ __launch_bounds__(256) void gemm_tf32(
    const float* __restrict__ A, const float* __restrict__ B,
    float* __restrict__ C, int M, int N, int K)
{
    if constexpr (IN_O) A = g_O;

    __shared__ float As[128][40];   // pad 8 -> 16B-aligned rows, 2-way frag conflicts
    __shared__ float Bs[32][136];   // pad 8 -> conflict-free B-frag loads

    const int tid  = threadIdx.x;
    const int lane = tid & 31;
    const int w    = tid >> 5;
    const int wr   = w >> 2;        // 0..1 : warp row  (64 rows)
    const int wc   = w & 3;         // 0..3 : warp col  (32 cols)
    const int g    = lane >> 2;     // groupID
    const int tg   = lane & 3;      // thread-in-group
    const int bm0  = blockIdx.y * 128;
    const int bn0  = blockIdx.x * 128;

    float acc[4][4][4];
#pragma unroll
    for (int mt = 0; mt < 4; mt++)
#pragma unroll
        for (int nt = 0; nt < 4; nt++)
#pragma unroll
            for (int q = 0; q < 4; q++) acc[mt][nt][q] = 0.f;

    for (int kb = 0; kb < K; kb += 32) {
        // load A tile 128x32 (float4)
#pragma unroll
        for (int i = 0; i < 4; i++) {
            int f = tid + i * 256;
            int r = f >> 3, c = (f & 7) << 2;
            float4 v = *(const float4*)(A + (long)(bm0 + r) * K + kb + c);
            *(float4*)&As[r][c] = v;
        }
        // load B tile 32x128 (float4)
#pragma unroll
        for (int i = 0; i < 4; i++) {
            int f = tid + i * 256;
            int r = f >> 5, c = (f & 31) << 2;
            float4 v = *(const float4*)(B + (long)(kb + r) * N + bn0 + c);
            *(float4*)&Bs[r][c] = v;
        }
        __syncthreads();

#pragma unroll
        for (int ks = 0; ks < 4; ks++) {
            const int k0 = ks * 8;
            unsigned af[4][4], bf[4][2];
#pragma unroll
            for (int mt = 0; mt < 4; mt++) {
                int r = wr * 64 + mt * 16 + g;
                af[mt][0] = f2tf32(As[r    ][k0 + tg    ]);
                af[mt][1] = f2tf32(As[r + 8][k0 + tg    ]);
                af[mt][2] = f2tf32(As[r    ][k0 + tg + 4]);
                af[mt][3] = f2tf32(As[r + 8][k0 + tg + 4]);
            }
#pragma unroll
            for (int nt = 0; nt < 4; nt++) {
                int c = wc * 32 + nt * 8 + g;
                bf[nt][0] = f2tf32(Bs[k0 + tg    ][c]);
                bf[nt][1] = f2tf32(Bs[k0 + tg + 4][c]);
            }
#pragma unroll
            for (int mt = 0; mt < 4; mt++)
#pragma unroll
                for (int nt = 0; nt < 4; nt++)
                    mma8(acc[mt][nt], af[mt], bf[nt]);
        }
        __syncthreads();
    }

    // epilogue
#pragma unroll
    for (int mt = 0; mt < 4; mt++) {
#pragma unroll
        for (int nt = 0; nt < 4; nt++) {
            int row = bm0 + wr * 64 + mt * 16 + g;
            int col = bn0 + wc * 32 + nt * 8 + 2 * tg;
            if constexpr (!OUT_QKV) {
                *(float2*)(C + (long)row * N + col) =
                    make_float2(acc[mt][nt][0], acc[mt][nt][1]);
                *(float2*)(C + (long)(row + 8) * N + col) =
                    make_float2(acc[mt][nt][2], acc[mt][nt][3]);
            } else {
                int which = col >> 10;           // 0=K, 1=Q, 2=V
                int cc = col & 1023;
                int h = cc >> 6, d = cc & 63;
                int b = row >> 11, t = row & 2047;  // tiles never straddle batch
                float* dst = (which == 0) ? g_K : ((which == 1) ? g_Q : g_V);
                int base = ((b * HH + h) * TT + t) * HSZ + d;
                *(float2*)(dst + base) =
                    make_float2(acc[mt][nt][0], acc[mt][nt][1]);
                *(float2*)(dst + base + 8 * HSZ) =
                    make_float2(acc[mt][nt][2], acc[mt][nt][3]);
            }
        }
    }
}

// ---------------------------------------------------------------------------
// Flash attention (causal). Grid: (T/64, B*H). Block: 128 threads (4 warps).
// Each warp owns 16 q-rows of a 64-row q-tile. KV tiles of 64.
// Smem: 3 x 64x64 fp32 buffers (Q reused as P after frag extraction) = 48 KB.
// XOR swizzle: element (r, c) stored at r*64 + (c ^ ((r & 3) << 3)).
// ---------------------------------------------------------------------------
__global__ __launch_bounds__(128) void attn_kernel()
{
    __shared__ float QP[64 * 64];
    __shared__ float Ks[64 * 64];
    __shared__ float Vs[64 * 64];

    const int tid  = threadIdx.x;
    const int lane = tid & 31;
    const int w    = tid >> 5;         // warp 0..3
    const int g    = lane >> 2;        // groupID 0..7
    const int tg   = lane & 3;
    const int qi   = blockIdx.x;       // q-tile
    const int bh   = blockIdx.y;       // b*H + h

    const float* Qg = g_Q + (long)bh * TT * HSZ;
    const float* Kg = g_K + (long)bh * TT * HSZ;
    const float* Vg = g_V + (long)bh * TT * HSZ;

    // load Q tile (swizzled)
#pragma unroll
    for (int i = 0; i < 16; i++) {
        int f = tid + i * 128;
        int r = f >> 5, d = (f & 31) << 1;
        float2 v = *(const float2*)(Qg + (long)(qi * 64 + r) * HSZ + d);
        *(float2*)&QP[r * 64 + (d ^ ((r & 3) << 3))] = v;
    }
    __syncthreads();

    // extract this warp's Q A-fragments once (rows w*16+g and +8 only)
    unsigned qa[8][4];
    {
        const int r = w * 16 + g;
        const int x = (r & 3) << 3;    // (r+8)&3 == r&3
#pragma unroll
        for (int kt = 0; kt < 8; kt++) {
            int k0 = kt * 8;
            qa[kt][0] = f2tf32(QP[ r      * 64 + ((k0 + tg    ) ^ x)]);
            qa[kt][1] = f2tf32(QP[(r + 8) * 64 + ((k0 + tg    ) ^ x)]);
            qa[kt][2] = f2tf32(QP[ r      * 64 + ((k0 + tg + 4) ^ x)]);
            qa[kt][3] = f2tf32(QP[(r + 8) * 64 + ((k0 + tg + 4) ^ x)]);
        }
    }
    // QP rows are warp-private from here on (P reuses exactly this warp's rows)

    float o[8][4];
#pragma unroll
    for (int nt = 0; nt < 8; nt++)
#pragma unroll
        for (int q = 0; q < 4; q++) o[nt][q] = 0.f;
    float mrow0 = -1e30f, mrow1 = -1e30f;
    float lrow0 = 0.f,    lrow1 = 0.f;
    const float SCL2E = (1.0f / 32.0f) * 1.4426950408889634f; // scale * log2(e)
    const int qg0 = qi * 64 + w * 16 + g;

    for (int j = 0; j <= qi; j++) {
        __syncthreads();  // all warps done with previous Ks/Vs
        // load K, V tiles (swizzled)
#pragma unroll
        for (int i = 0; i < 16; i++) {
            int f = tid + i * 128;
            int r = f >> 5, d = (f & 31) << 1;
            int sw = r * 64 + (d ^ ((r & 3) << 3));
            *(float2*)&Ks[sw] = *(const float2*)(Kg + (long)(j * 64 + r) * HSZ + d);
            *(float2*)&Vs[sw] = *(const float2*)(Vg + (long)(j * 64 + r) * HSZ + d);
        }
        __syncthreads();

        // S = Q @ K^T  (k-dim = head dim)
        float s[8][4];
#pragma unroll
        for (int nt = 0; nt < 8; nt++)
#pragma unroll
            for (int q = 0; q < 4; q++) s[nt][q] = 0.f;
#pragma unroll
        for (int kt = 0; kt < 8; kt++) {
            int k0 = kt * 8;
#pragma unroll
            for (int nt = 0; nt < 8; nt++) {
                int kp = nt * 8 + g;
                int base = kp * 64, x = (kp & 3) << 3;
                unsigned bf[2];
                bf[0] = f2tf32(Ks[base + ((k0 + tg    ) ^ x)]);
                bf[1] = f2tf32(Ks[base + ((k0 + tg + 4) ^ x)]);
                mma8(s[nt], qa[kt], bf);
            }
        }

        // causal mask (only the diagonal tile can mask)
        if (j == qi) {
#pragma unroll
            for (int nt = 0; nt < 8; nt++) {
                int kg = j * 64 + nt * 8 + 2 * tg;
                if (kg     > qg0    ) s[nt][0] = -1e30f;
                if (kg + 1 > qg0    ) s[nt][1] = -1e30f;
                if (kg     > qg0 + 8) s[nt][2] = -1e30f;
                if (kg + 1 > qg0 + 8) s[nt][3] = -1e30f;
            }
        }

        // online softmax (rows qg0 and qg0+8 per thread-quad)
        float rm0 = -1e30f, rm1 = -1e30f;
#pragma unroll
        for (int nt = 0; nt < 8; nt++) {
            rm0 = fmaxf(rm0, fmaxf(s[nt][0], s[nt][1]));
            rm1 = fmaxf(rm1, fmaxf(s[nt][2], s[nt][3]));
        }
        rm0 = fmaxf(rm0, __shfl_xor_sync(0xffffffffu, rm0, 1));
        rm0 = fmaxf(rm0, __shfl_xor_sync(0xffffffffu, rm0, 2));
        rm1 = fmaxf(rm1, __shfl_xor_sync(0xffffffffu, rm1, 1));
        rm1 = fmaxf(rm1, __shfl_xor_sync(0xffffffffu, rm1, 2));

        float mn0 = fmaxf(mrow0, rm0), mn1 = fmaxf(mrow1, rm1);
        float f0 = exp2f((mrow0 - mn0) * SCL2E);
        float f1 = exp2f((mrow1 - mn1) * SCL2E);
        mrow0 = mn0; mrow1 = mn1;

        float sum0 = 0.f, sum1 = 0.f;
        {
            const int r = w * 16 + g;
            const int x = (r & 3) << 3;
#pragma unroll
            for (int nt = 0; nt < 8; nt++) {
                float p0 = exp2f((s[nt][0] - mn0) * SCL2E);
                float p1 = exp2f((s[nt][1] - mn0) * SCL2E);
                float p2 = exp2f((s[nt][2] - mn1) * SCL2E);
                float p3 = exp2f((s[nt][3] - mn1) * SCL2E);
                sum0 += p0 + p1;
                sum1 += p2 + p3;
                int c = nt * 8 + 2 * tg;
                *(float2*)&QP[ r      * 64 + (c ^ x)] = make_float2(p0, p1);
                *(float2*)&QP[(r + 8) * 64 + (c ^ x)] = make_float2(p2, p3);
            }
        }
        sum0 += __shfl_xor_sync(0xffffffffu, sum0, 1);
        sum0 += __shfl_xor_sync(0xffffffffu, sum0, 2);
        sum1 += __shfl_xor_sync(0xffffffffu, sum1, 1);
        sum1 += __shfl_xor_sync(0xffffffffu, sum1, 2);
        lrow0 = lrow0 * f0 + sum0;
        lrow1 = lrow1 * f1 + sum1;

#pragma unroll
        for (int nt = 0; nt < 8; nt++) {
            o[nt][0] *= f0; o[nt][1] *= f0;
            o[nt][2] *= f1; o[nt][3] *= f1;
        }
        __syncwarp();

        // O += P @ V   (k-dim = key positions)
        {
            const int r = w * 16 + g;
            const int x = (r & 3) << 3;
#pragma unroll
            for (int kt = 0; kt < 8; kt++) {
                int k0 = kt * 8;
                unsigned pa[4];
                pa[0] = f2tf32(QP[ r      * 64 + ((k0 + tg    ) ^ x)]);
                pa[1] = f2tf32(QP[(r + 8) * 64 + ((k0 + tg    ) ^ x)]);
                pa[2] = f2tf32(QP[ r      * 64 + ((k0 + tg + 4) ^ x)]);
                pa[3] = f2tf32(QP[(r + 8) * 64 + ((k0 + tg + 4) ^ x)]);
                int kp0 = k0 + tg;
                int xv = (kp0 & 3) << 3;   // (kp0+4)&3 == kp0&3
#pragma unroll
                for (int nt = 0; nt < 8; nt++) {
                    int d = nt * 8 + g;
                    unsigned vb[2];
                    vb[0] = f2tf32(Vs[ kp0      * 64 + (d ^ xv)]);
                    vb[1] = f2tf32(Vs[(kp0 + 4) * 64 + (d ^ xv)]);
                    mma8(o[nt], pa, vb);
                }
            }
        }
    }

    // finalize: divide by l, write O in [b, t, c] layout
    float il0 = 1.0f / lrow0;
    float il1 = 1.0f / lrow1;
    const int b = bh >> 4, h = bh & 15;
    const int row0 = qi * 64 + w * 16 + g;
#pragma unroll
    for (int nt = 0; nt < 8; nt++) {
        int d = nt * 8 + 2 * tg;
        long idx0 = ((long)(b * TT + row0    ) * CCH) + h * HSZ + d;
        long idx1 = ((long)(b * TT + row0 + 8) * CCH) + h * HSZ + d;
        *(float2*)(g_O + idx0) = make_float2(o[nt][0] * il0, o[nt][1] * il0);
        *(float2*)(g_O + idx1) = make_float2(o[nt][2] * il1, o[nt][3] * il1);
    }
}

// ---------------------------------------------------------------------------
extern "C" void kernel_launch(void* const* d_in, const int* in_sizes, int n_in,
                              void* d_out, int out_size)
{
    (void)in_sizes; (void)n_in; (void)out_size;
    const float* X     = (const float*)d_in[0];
    const float* Wqkv  = (const float*)d_in[1];
    const float* Wproj = (const float*)d_in[2];
    float* out = (float*)d_out;

    // 1) QKV = X @ W_qkv, scattered to g_K/g_Q/g_V in [b,h,t,hs]
    gemm_tf32<0, 1><<<dim3(3 * CCH / 128, BB * TT / 128), 256>>>(
        X, Wqkv, nullptr, BB * TT, 3 * CCH, CCH);

    // 2) causal flash attention -> g_O [b,t,c]
    attn_kernel<<<dim3(TT / 64, BB * HH), 128>>>();

    // 3) out = g_O @ W_proj
    gemm_tf32<1, 0><<<dim3(CCH / 128, BB * TT / 128), 256>>>(
        nullptr, Wproj, out, BB * TT, CCH, CCH);
}

// round 4
// speedup vs baseline: 1.1897x; 1.1897x over previous
#include <cuda_runtime.h>
#include <math.h>

#define BB  2
#define TT  2048
#define CCH 1024
#define HH  16
#define HSZ 64

// Scratch (alloc-free rule: __device__ globals). 16 MB each + 16 MB O = 64 MB.
__device__ float g_K[BB * HH * TT * HSZ];
__device__ float g_Q[BB * HH * TT * HSZ];
__device__ float g_V[BB * HH * TT * HSZ];
__device__ float g_O[BB * TT * CCH];

__device__ __forceinline__ unsigned f2tf32(float f) {
    unsigned u;
    asm("cvt.rna.tf32.f32 %0, %1;" : "=r"(u) : "f"(f));
    return u;
}

__device__ __forceinline__ void mma8(float* c, const unsigned* a, const unsigned* b) {
    asm volatile(
        "mma.sync.aligned.m16n8k8.row.col.f32.tf32.tf32.f32 "
        "{%0,%1,%2,%3}, {%4,%5,%6,%7}, {%8,%9}, {%0,%1,%2,%3};\n"
        : "+f"(c[0]), "+f"(c[1]), "+f"(c[2]), "+f"(c[3])
        : "r"(a[0]), "r"(a[1]), "r"(a[2]), "r"(a[3]), "r"(b[0]), "r"(b[1]));
}

__device__ __forceinline__ void cpa16(float* s, const float* g) {
    unsigned sa = (unsigned)__cvta_generic_to_shared(s);
    asm volatile("cp.async.cg.shared.global [%0], [%1], 16;\n" :: "r"(sa), "l"(g));
}
__device__ __forceinline__ void cp_commit() {
    asm volatile("cp.async.commit_group;\n");
}
template <int N>
__device__ __forceinline__ void cp_wait() {
    asm volatile("cp.async.wait_group %0;\n" :: "n"(N));
}

// ---------------------------------------------------------------------------
// TF32 GEMM: C[M,N] = A[M,K] @ B[K,N], row-major. 2-stage cp.async pipeline.
// IN_O:    1 -> A read from g_O.
// OUT_QKV: 1 -> scatter columns [0,C)->g_K, [C,2C)->g_Q, [2C,3C)->g_V in
//               [b,h,t,hs] layout (module order: K, Q, V).
// Block 256 threads (8 warps, 2x4), tile 128x128, BK=32.
// Smem strides: A=36 floats (A-frag LDS conflict-free: (4g+tg)%32 distinct),
//               B=136 floats (B-frag: (8tg+g)%32 distinct).
// ---------------------------------------------------------------------------
#define GA_STRIDE 36
#define GB_STRIDE 136
#define GA_SZ (128 * GA_STRIDE)
#define GB_SZ (32 * GB_STRIDE)
#define GEMM_SMEM ((2 * GA_SZ + 2 * GB_SZ) * 4)

template <int IN_O, int OUT_QKV>
__global__ __launch_bounds__(256) void gemm_tf32(
    const float* __restrict__ A, const float* __restrict__ B,
    float* __restrict__ C, int M, int N, int K)
{
    if constexpr (IN_O) A = g_O;

    extern __shared__ float smem[];
    float* As = smem;                  // [2][128][36]
    float* Bs = smem + 2 * GA_SZ;      // [2][32][136]

    const int tid  = threadIdx.x;
    const int lane = tid & 31;
    const int w    = tid >> 5;
    const int wr   = w >> 2;        // 0..1 : warp row  (64 rows)
    const int wc   = w & 3;         // 0..3 : warp col  (32 cols)
    const int g    = lane >> 2;     // groupID
    const int tg   = lane & 3;      // thread-in-group
    const int bm0  = blockIdx.y * 128;
    const int bn0  = blockIdx.x * 128;

    float acc[4][4][4];
#pragma unroll
    for (int mt = 0; mt < 4; mt++)
#pragma unroll
        for (int nt = 0; nt < 4; nt++)
#pragma unroll
            for (int q = 0; q < 4; q++) acc[mt][nt][q] = 0.f;

    // per-thread load coordinates (4 x 16B for A, 4 x 16B for B)
    const int ar = tid >> 3, ac = (tid & 7) << 2;      // A: rows of 32
    const int br = tid >> 5, bc = (tid & 31) << 2;     // B: rows of 128

    auto issue_tile = [&](int st, int kb) {
        float* Ad = As + st * GA_SZ;
        float* Bd = Bs + st * GB_SZ;
#pragma unroll
        for (int i = 0; i < 4; i++) {
            int r = ar + i * 32;
            cpa16(Ad + r * GA_STRIDE + ac,
                  A + (long)(bm0 + r) * K + kb + ac);
        }
#pragma unroll
        for (int i = 0; i < 4; i++) {
            int r = br + i * 8;
            cpa16(Bd + r * GB_STRIDE + bc,
                  B + (long)(kb + r) * N + bn0 + bc);
        }
    };

    const int nk = K / 32;
    issue_tile(0, 0);
    cp_commit();

    for (int t = 0; t < nk; t++) {
        if (t + 1 < nk) {
            issue_tile((t + 1) & 1, (t + 1) * 32);
            cp_commit();
            cp_wait<1>();
        } else {
            cp_wait<0>();
        }
        __syncthreads();

        const float* As0 = As + (t & 1) * GA_SZ;
        const float* Bs0 = Bs + (t & 1) * GB_SZ;
#pragma unroll
        for (int ks = 0; ks < 4; ks++) {
            const int k0 = ks * 8;
            unsigned af[4][4], bf[4][2];
#pragma unroll
            for (int mt = 0; mt < 4; mt++) {
                int r = wr * 64 + mt * 16 + g;
                af[mt][0] = f2tf32(As0[ r      * GA_STRIDE + k0 + tg    ]);
                af[mt][1] = f2tf32(As0[(r + 8) * GA_STRIDE + k0 + tg    ]);
                af[mt][2] = f2tf32(As0[ r      * GA_STRIDE + k0 + tg + 4]);
                af[mt][3] = f2tf32(As0[(r + 8) * GA_STRIDE + k0 + tg + 4]);
            }
#pragma unroll
            for (int nt = 0; nt < 4; nt++) {
                int c = wc * 32 + nt * 8 + g;
                bf[nt][0] = f2tf32(Bs0[(k0 + tg    ) * GB_STRIDE + c]);
                bf[nt][1] = f2tf32(Bs0[(k0 + tg + 4) * GB_STRIDE + c]);
            }
#pragma unroll
            for (int mt = 0; mt < 4; mt++)
#pragma unroll
                for (int nt = 0; nt < 4; nt++)
                    mma8(acc[mt][nt], af[mt], bf[nt]);
        }
        __syncthreads();   // before next iter overwrites stage t&1
    }

    // epilogue
#pragma unroll
    for (int mt = 0; mt < 4; mt++) {
#pragma unroll
        for (int nt = 0; nt < 4; nt++) {
            int row = bm0 + wr * 64 + mt * 16 + g;
            int col = bn0 + wc * 32 + nt * 8 + 2 * tg;
            if constexpr (!OUT_QKV) {
                *(float2*)(C + (long)row * N + col) =
                    make_float2(acc[mt][nt][0], acc[mt][nt][1]);
                *(float2*)(C + (long)(row + 8) * N + col) =
                    make_float2(acc[mt][nt][2], acc[mt][nt][3]);
            } else {
                int which = col >> 10;           // 0=K, 1=Q, 2=V
                int cc = col & 1023;
                int h = cc >> 6, d = cc & 63;
                int b = row >> 11, t = row & 2047;
                float* dst = (which == 0) ? g_K : ((which == 1) ? g_Q : g_V);
                int base = ((b * HH + h) * TT + t) * HSZ + d;
                *(float2*)(dst + base) =
                    make_float2(acc[mt][nt][0], acc[mt][nt][1]);
                *(float2*)(dst + base + 8 * HSZ) =
                    make_float2(acc[mt][nt][2], acc[mt][nt][3]);
            }
        }
    }
}

// ---------------------------------------------------------------------------
// Flash attention (causal). Grid: (T/64, B*H). Block: 128 threads (4 warps).
// Each warp owns 16 q-rows of a 64-row q-tile. KV tiles of 64, 2-stage
// cp.async double buffering. qi reversed so the longest CTAs launch first.
// Smem: QP (16KB) + 2xK (32KB) + 2xV (32KB) = 80KB dynamic.
// XOR swizzle: element (r, c) at r*64 + (c ^ ((r & 3) << 3)).
// ---------------------------------------------------------------------------
#define ATTN_SMEM (5 * 64 * 64 * 4)

__global__ __launch_bounds__(128) void attn_kernel()
{
    extern __shared__ float asmem[];
    float* QP = asmem;                 // 64*64
    float* Ks = asmem + 4096;          // [2][64*64]
    float* Vs = asmem + 3 * 4096;      // [2][64*64]

    const int tid  = threadIdx.x;
    const int lane = tid & 31;
    const int w    = tid >> 5;         // warp 0..3
    const int g    = lane >> 2;        // groupID 0..7
    const int tg   = lane & 3;
    const int qi   = gridDim.x - 1 - blockIdx.x;   // longest first
    const int bh   = blockIdx.y;       // b*H + h

    const float* Qg = g_Q + (long)bh * TT * HSZ;
    const float* Kg = g_K + (long)bh * TT * HSZ;
    const float* Vg = g_V + (long)bh * TT * HSZ;

    auto issue_kv = [&](int j, int st) {
#pragma unroll
        for (int i = 0; i < 8; i++) {
            int f = tid + i * 128;
            int r = f >> 4, d = (f & 15) << 2;
            int sw = st * 4096 + r * 64 + (d ^ ((r & 3) << 3));
            cpa16(Ks + sw, Kg + (long)(j * 64 + r) * HSZ + d);
            cpa16(Vs + sw, Vg + (long)(j * 64 + r) * HSZ + d);
        }
    };

    // start KV tile 0 immediately
    issue_kv(0, 0);
    cp_commit();

    // load Q tile (swizzled)
#pragma unroll
    for (int i = 0; i < 16; i++) {
        int f = tid + i * 128;
        int r = f >> 5, d = (f & 31) << 1;
        float2 v = *(const float2*)(Qg + (long)(qi * 64 + r) * HSZ + d);
        *(float2*)&QP[r * 64 + (d ^ ((r & 3) << 3))] = v;
    }
    __syncthreads();

    // extract this warp's Q A-fragments once (rows w*16+g and +8 only)
    unsigned qa[8][4];
    {
        const int r = w * 16 + g;
        const int x = (r & 3) << 3;    // (r+8)&3 == r&3
#pragma unroll
        for (int kt = 0; kt < 8; kt++) {
            int k0 = kt * 8;
            qa[kt][0] = f2tf32(QP[ r      * 64 + ((k0 + tg    ) ^ x)]);
            qa[kt][1] = f2tf32(QP[(r + 8) * 64 + ((k0 + tg    ) ^ x)]);
            qa[kt][2] = f2tf32(QP[ r      * 64 + ((k0 + tg + 4) ^ x)]);
            qa[kt][3] = f2tf32(QP[(r + 8) * 64 + ((k0 + tg + 4) ^ x)]);
        }
    }
    // QP rows are warp-private from here on (P reuses exactly this warp's rows)

    float o[8][4];
#pragma unroll
    for (int nt = 0; nt < 8; nt++)
#pragma unroll
        for (int q = 0; q < 4; q++) o[nt][q] = 0.f;
    float mrow0 = -1e30f, mrow1 = -1e30f;
    float lrow0 = 0.f,    lrow1 = 0.f;
    const float SCL2E = (1.0f / 32.0f) * 1.4426950408889634f; // scale * log2(e)
    const int qg0 = qi * 64 + w * 16 + g;

    for (int j = 0; j <= qi; j++) {
        if (j < qi) {
            issue_kv(j + 1, (j + 1) & 1);
            cp_commit();
            cp_wait<1>();
        } else {
            cp_wait<0>();
        }
        __syncthreads();

        const float* Kc = Ks + (j & 1) * 4096;
        const float* Vc = Vs + (j & 1) * 4096;

        // S = Q @ K^T  (k-dim = head dim)
        float s[8][4];
#pragma unroll
        for (int nt = 0; nt < 8; nt++)
#pragma unroll
            for (int q = 0; q < 4; q++) s[nt][q] = 0.f;
#pragma unroll
        for (int kt = 0; kt < 8; kt++) {
            int k0 = kt * 8;
#pragma unroll
            for (int nt = 0; nt < 8; nt++) {
                int kp = nt * 8 + g;
                int base = kp * 64, x = (kp & 3) << 3;
                unsigned bf[2];
                bf[0] = f2tf32(Kc[base + ((k0 + tg    ) ^ x)]);
                bf[1] = f2tf32(Kc[base + ((k0 + tg + 4) ^ x)]);
                mma8(s[nt], qa[kt], bf);
            }
        }

        // causal mask (only the diagonal tile can mask)
        if (j == qi) {
#pragma unroll
            for (int nt = 0; nt < 8; nt++) {
                int kg = j * 64 + nt * 8 + 2 * tg;
                if (kg     > qg0    ) s[nt][0] = -1e30f;
                if (kg + 1 > qg0    ) s[nt][1] = -1e30f;
                if (kg     > qg0 + 8) s[nt][2] = -1e30f;
                if (kg + 1 > qg0 + 8) s[nt][3] = -1e30f;
            }
        }

        // online softmax (rows qg0 and qg0+8 per thread-quad)
        float rm0 = -1e30f, rm1 = -1e30f;
#pragma unroll
        for (int nt = 0; nt < 8; nt++) {
            rm0 = fmaxf(rm0, fmaxf(s[nt][0], s[nt][1]));
            rm1 = fmaxf(rm1, fmaxf(s[nt][2], s[nt][3]));
        }
        rm0 = fmaxf(rm0, __shfl_xor_sync(0xffffffffu, rm0, 1));
        rm0 = fmaxf(rm0, __shfl_xor_sync(0xffffffffu, rm0, 2));
        rm1 = fmaxf(rm1, __shfl_xor_sync(0xffffffffu, rm1, 1));
        rm1 = fmaxf(rm1, __shfl_xor_sync(0xffffffffu, rm1, 2));

        float mn0 = fmaxf(mrow0, rm0), mn1 = fmaxf(mrow1, rm1);
        float f0 = exp2f((mrow0 - mn0) * SCL2E);
        float f1 = exp2f((mrow1 - mn1) * SCL2E);
        mrow0 = mn0; mrow1 = mn1;

        float sum0 = 0.f, sum1 = 0.f;
        {
            const int r = w * 16 + g;
            const int x = (r & 3) << 3;
#pragma unroll
            for (int nt = 0; nt < 8; nt++) {
                float p0 = exp2f((s[nt][0] - mn0) * SCL2E);
                float p1 = exp2f((s[nt][1] - mn0) * SCL2E);
                float p2 = exp2f((s[nt][2] - mn1) * SCL2E);
                float p3 = exp2f((s[nt][3] - mn1) * SCL2E);
                sum0 += p0 + p1;
                sum1 += p2 + p3;
                int c = nt * 8 + 2 * tg;
                *(float2*)&QP[ r      * 64 + (c ^ x)] = make_float2(p0, p1);
                *(float2*)&QP[(r + 8) * 64 + (c ^ x)] = make_float2(p2, p3);
            }
        }
        sum0 += __shfl_xor_sync(0xffffffffu, sum0, 1);
        sum0 += __shfl_xor_sync(0xffffffffu, sum0, 2);
        sum1 += __shfl_xor_sync(0xffffffffu, sum1, 1);
        sum1 += __shfl_xor_sync(0xffffffffu, sum1, 2);
        lrow0 = lrow0 * f0 + sum0;
        lrow1 = lrow1 * f1 + sum1;

#pragma unroll
        for (int nt = 0; nt < 8; nt++) {
            o[nt][0] *= f0; o[nt][1] *= f0;
            o[nt][2] *= f1; o[nt][3] *= f1;
        }
        __syncwarp();

        // O += P @ V   (k-dim = key positions)
        {
            const int r = w * 16 + g;
            const int x = (r & 3) << 3;
#pragma unroll
            for (int kt = 0; kt < 8; kt++) {
                int k0 = kt * 8;
                unsigned pa[4];
                pa[0] = f2tf32(QP[ r      * 64 + ((k0 + tg    ) ^ x)]);
                pa[1] = f2tf32(QP[(r + 8) * 64 + ((k0 + tg    ) ^ x)]);
                pa[2] = f2tf32(QP[ r      * 64 + ((k0 + tg + 4) ^ x)]);
                pa[3] = f2tf32(QP[(r + 8) * 64 + ((k0 + tg + 4) ^ x)]);
                int kp0 = k0 + tg;
                int xv = (kp0 & 3) << 3;   // (kp0+4)&3 == kp0&3
#pragma unroll
                for (int nt = 0; nt < 8; nt++) {
                    int d = nt * 8 + g;
                    unsigned vb[2];
                    vb[0] = f2tf32(Vc[ kp0      * 64 + (d ^ xv)]);
                    vb[1] = f2tf32(Vc[(kp0 + 4) * 64 + (d ^ xv)]);
                    mma8(o[nt], pa, vb);
                }
            }
        }
        __syncthreads();   // before next iter's cp.async overwrites stage (j+1)&1
    }

    // finalize: divide by l, write O in [b, t, c] layout
    float il0 = 1.0f / lrow0;
    float il1 = 1.0f / lrow1;
    const int b = bh >> 4, h = bh & 15;
    const int row0 = qi * 64 + w * 16 + g;
#pragma unroll
    for (int nt = 0; nt < 8; nt++) {
        int d = nt * 8 + 2 * tg;
        long idx0 = ((long)(b * TT + row0    ) * CCH) + h * HSZ + d;
        long idx1 = ((long)(b * TT + row0 + 8) * CCH) + h * HSZ + d;
        *(float2*)(g_O + idx0) = make_float2(o[nt][0] * il0, o[nt][1] * il0);
        *(float2*)(g_O + idx1) = make_float2(o[nt][2] * il1, o[nt][3] * il1);
    }
}

// ---------------------------------------------------------------------------
extern "C" void kernel_launch(void* const* d_in, const int* in_sizes, int n_in,
                              void* d_out, int out_size)
{
    (void)in_sizes; (void)n_in; (void)out_size;
    const float* X     = (const float*)d_in[0];
    const float* Wqkv  = (const float*)d_in[1];
    const float* Wproj = (const float*)d_in[2];
    float* out = (float*)d_out;

    static bool attrs_set = false;
    if (!attrs_set) {
        cudaFuncSetAttribute(gemm_tf32<0, 1>,
            cudaFuncAttributeMaxDynamicSharedMemorySize, GEMM_SMEM);
        cudaFuncSetAttribute(gemm_tf32<1, 0>,
            cudaFuncAttributeMaxDynamicSharedMemorySize, GEMM_SMEM);
        cudaFuncSetAttribute(attn_kernel,
            cudaFuncAttributeMaxDynamicSharedMemorySize, ATTN_SMEM);
        attrs_set = true;
    }

    // 1) QKV = X @ W_qkv, scattered to g_K/g_Q/g_V in [b,h,t,hs]
    gemm_tf32<0, 1><<<dim3(3 * CCH / 128, BB * TT / 128), 256, GEMM_SMEM>>>(
        X, Wqkv, nullptr, BB * TT, 3 * CCH, CCH);

    // 2) causal flash attention -> g_O [b,t,c]
    attn_kernel<<<dim3(TT / 64, BB * HH), 128, ATTN_SMEM>>>();

    // 3) out = g_O @ W_proj
    gemm_tf32<1, 0><<<dim3(CCH / 128, BB * TT / 128), 256, GEMM_SMEM>>>(
        nullptr, Wproj, out, BB * TT, CCH, CCH);
}

// round 7
// speedup vs baseline: 1.2528x; 1.0530x over previous
#include <cuda_runtime.h>
#include <math.h>

#define BB  2
#define TT  2048
#define CCH 1024
#define HH  16
#define HSZ 64

// Scratch (alloc-free rule: __device__ globals).
__device__ float g_K[BB * HH * TT * HSZ];
__device__ float g_Q[BB * HH * TT * HSZ];
__device__ float g_V[BB * HH * TT * HSZ];
__device__ float g_O[BB * TT * CCH];
// tf32-pre-rounded copies of the inputs (rounded once, read many times).
__device__ float g_Xc[BB * TT * CCH];
__device__ float g_Wqkvc[CCH * 3 * CCH];
__device__ float g_Wprojc[CCH * CCH];

__device__ __forceinline__ unsigned f2tf32(float f) {
    unsigned u;
    asm("cvt.rna.tf32.f32 %0, %1;" : "=r"(u) : "f"(f));
    return u;
}
__device__ __forceinline__ float rnd32(float f) {
    return __uint_as_float(f2tf32(f));
}
// fast exp2 via MUFU (ex2.approx)
__device__ __forceinline__ float fex2(float x) {
    float r;
    asm("ex2.approx.f32 %0, %1;" : "=f"(r) : "f"(x));
    return r;
}

__device__ __forceinline__ void mma8(float* c, const unsigned* a, const unsigned* b) {
    asm volatile(
        "mma.sync.aligned.m16n8k8.row.col.f32.tf32.tf32.f32 "
        "{%0,%1,%2,%3}, {%4,%5,%6,%7}, {%8,%9}, {%0,%1,%2,%3};\n"
        : "+f"(c[0]), "+f"(c[1]), "+f"(c[2]), "+f"(c[3])
        : "r"(a[0]), "r"(a[1]), "r"(a[2]), "r"(a[3]), "r"(b[0]), "r"(b[1]));
}

__device__ __forceinline__ void cpa16(float* s, const float* g) {
    unsigned sa = (unsigned)__cvta_generic_to_shared(s);
    asm volatile("cp.async.cg.shared.global [%0], [%1], 16;\n" :: "r"(sa), "l"(g));
}
__device__ __forceinline__ void cp_commit() {
    asm volatile("cp.async.commit_group;\n");
}
template <int N>
__device__ __forceinline__ void cp_wait() {
    asm volatile("cp.async.wait_group %0;\n" :: "n"(N));
}

// ---------------------------------------------------------------------------
// Prepass: round inputs to tf32 once. DST: 0->g_Xc, 1->g_Wqkvc, 2->g_Wprojc.
// ---------------------------------------------------------------------------
template <int DST>
__global__ void round_k(const float* __restrict__ in, int n)
{
    float* out = (DST == 0) ? g_Xc : ((DST == 1) ? g_Wqkvc : g_Wprojc);
    int i = (blockIdx.x * blockDim.x + threadIdx.x) * 4;
    if (i < n) {
        float4 v = *(const float4*)(in + i);
        v.x = rnd32(v.x); v.y = rnd32(v.y);
        v.z = rnd32(v.z); v.w = rnd32(v.w);
        *(float4*)(out + i) = v;
    }
}

// ---------------------------------------------------------------------------
// TF32 GEMM: C[M,N] = A[M,K] @ B[K,N], row-major, 2-stage cp.async.
// MODE 0: A=g_Xc, B=g_Wqkvc, scatter to g_K/g_Q/g_V (tf32-rounded) [b,h,t,hs].
// MODE 1: A=g_O,  B=g_Wprojc, C=out (raw fp32, final result).
// Inputs are pre-rounded -> NO cvt in the mainloop.
// Block 256 threads (8 warps 2x4), tile 128x128, BK=32.
// ---------------------------------------------------------------------------
#define GA_STRIDE 36
#define GB_STRIDE 136
#define GA_SZ (128 * GA_STRIDE)
#define GB_SZ (32 * GB_STRIDE)
#define GEMM_SMEM ((2 * GA_SZ + 2 * GB_SZ) * 4)

template <int MODE>
__global__ __launch_bounds__(256, 2) void gemm_tf32(float* __restrict__ C)
{
    const float* A = (MODE == 0) ? g_Xc : g_O;
    const float* B = (MODE == 0) ? g_Wqkvc : g_Wprojc;
    const int K = CCH;
    const int N = (MODE == 0) ? 3 * CCH : CCH;

    extern __shared__ float smem[];
    float* As = smem;                  // [2][128][36]
    float* Bs = smem + 2 * GA_SZ;      // [2][32][136]

    const int tid  = threadIdx.x;
    const int lane = tid & 31;
    const int w    = tid >> 5;
    const int wr   = w >> 2;
    const int wc   = w & 3;
    const int g    = lane >> 2;
    const int tg   = lane & 3;
    const int bm0  = blockIdx.y * 128;
    const int bn0  = blockIdx.x * 128;

    float acc[4][4][4];
#pragma unroll
    for (int mt = 0; mt < 4; mt++)
#pragma unroll
        for (int nt = 0; nt < 4; nt++)
#pragma unroll
            for (int q = 0; q < 4; q++) acc[mt][nt][q] = 0.f;

    const int ar = tid >> 3, ac = (tid & 7) << 2;
    const int br = tid >> 5, bc = (tid & 31) << 2;

    auto issue_tile = [&](int st, int kb) {
        float* Ad = As + st * GA_SZ;
        float* Bd = Bs + st * GB_SZ;
#pragma unroll
        for (int i = 0; i < 4; i++) {
            int r = ar + i * 32;
            cpa16(Ad + r * GA_STRIDE + ac, A + (long)(bm0 + r) * K + kb + ac);
        }
#pragma unroll
        for (int i = 0; i < 4; i++) {
            int r = br + i * 8;
            cpa16(Bd + r * GB_STRIDE + bc, B + (long)(kb + r) * N + bn0 + bc);
        }
    };

    const int nk = K / 32;
    issue_tile(0, 0);
    cp_commit();

    for (int t = 0; t < nk; t++) {
        if (t + 1 < nk) {
            issue_tile((t + 1) & 1, (t + 1) * 32);
            cp_commit();
            cp_wait<1>();
        } else {
            cp_wait<0>();
        }
        __syncthreads();

        const float* As0 = As + (t & 1) * GA_SZ;
        const float* Bs0 = Bs + (t & 1) * GB_SZ;
#pragma unroll
        for (int ks = 0; ks < 4; ks++) {
            const int k0 = ks * 8;
            unsigned af[4][4], bf[4][2];
#pragma unroll
            for (int mt = 0; mt < 4; mt++) {
                int r = wr * 64 + mt * 16 + g;
                af[mt][0] = __float_as_uint(As0[ r      * GA_STRIDE + k0 + tg    ]);
                af[mt][1] = __float_as_uint(As0[(r + 8) * GA_STRIDE + k0 + tg    ]);
                af[mt][2] = __float_as_uint(As0[ r      * GA_STRIDE + k0 + tg + 4]);
                af[mt][3] = __float_as_uint(As0[(r + 8) * GA_STRIDE + k0 + tg + 4]);
            }
#pragma unroll
            for (int nt = 0; nt < 4; nt++) {
                int c = wc * 32 + nt * 8 + g;
                bf[nt][0] = __float_as_uint(Bs0[(k0 + tg    ) * GB_STRIDE + c]);
                bf[nt][1] = __float_as_uint(Bs0[(k0 + tg + 4) * GB_STRIDE + c]);
            }
#pragma unroll
            for (int mt = 0; mt < 4; mt++)
#pragma unroll
                for (int nt = 0; nt < 4; nt++)
                    mma8(acc[mt][nt], af[mt], bf[nt]);
        }
        __syncthreads();
    }

    // epilogue
#pragma unroll
    for (int mt = 0; mt < 4; mt++) {
#pragma unroll
        for (int nt = 0; nt < 4; nt++) {
            int row = bm0 + wr * 64 + mt * 16 + g;
            int col = bn0 + wc * 32 + nt * 8 + 2 * tg;
            if constexpr (MODE == 1) {
                *(float2*)(C + (long)row * N + col) =
                    make_float2(acc[mt][nt][0], acc[mt][nt][1]);
                *(float2*)(C + (long)(row + 8) * N + col) =
                    make_float2(acc[mt][nt][2], acc[mt][nt][3]);
            } else {
                // tf32-round at write: attention consumes raw bits
                int which = col >> 10;           // 0=K, 1=Q, 2=V
                int cc = col & 1023;
                int h = cc >> 6, d = cc & 63;
                int b = row >> 11, t = row & 2047;
                float* dst = (which == 0) ? g_K : ((which == 1) ? g_Q : g_V);
                int base = ((b * HH + h) * TT + t) * HSZ + d;
                *(float2*)(dst + base) =
                    make_float2(rnd32(acc[mt][nt][0]), rnd32(acc[mt][nt][1]));
                *(float2*)(dst + base + 8 * HSZ) =
                    make_float2(rnd32(acc[mt][nt][2]), rnd32(acc[mt][nt][3]));
            }
        }
    }
}

// ---------------------------------------------------------------------------
// Flash attention (causal). Grid: (T/64, B*H). Block: 128 threads (4 warps).
// K/Q/V are pre-rounded tf32 -> no cvt in the loop; P rounded once at store.
// 2-stage cp.async KV double-buffer; longest CTAs first.
// ---------------------------------------------------------------------------
#define ATTN_SMEM (5 * 64 * 64 * 4)

__global__ __launch_bounds__(128, 2) void attn_kernel()
{
    extern __shared__ float asmem[];
    float* QP = asmem;                 // 64*64
    float* Ks = asmem + 4096;          // [2][64*64]
    float* Vs = asmem + 3 * 4096;      // [2][64*64]

    const int tid  = threadIdx.x;
    const int lane = tid & 31;
    const int w    = tid >> 5;
    const int g    = lane >> 2;
    const int tg   = lane & 3;
    const int qi   = gridDim.x - 1 - blockIdx.x;   // longest first
    const int bh   = blockIdx.y;

    const float* Qg = g_Q + (long)bh * TT * HSZ;
    const float* Kg = g_K + (long)bh * TT * HSZ;
    const float* Vg = g_V + (long)bh * TT * HSZ;

    auto issue_kv = [&](int j, int st) {
#pragma unroll
        for (int i = 0; i < 8; i++) {
            int f = tid + i * 128;
            int r = f >> 4, d = (f & 15) << 2;
            int sw = st * 4096 + r * 64 + (d ^ ((r & 3) << 3));
            cpa16(Ks + sw, Kg + (long)(j * 64 + r) * HSZ + d);
            cpa16(Vs + sw, Vg + (long)(j * 64 + r) * HSZ + d);
        }
    };

    issue_kv(0, 0);
    cp_commit();

    // load Q tile (swizzled)
#pragma unroll
    for (int i = 0; i < 16; i++) {
        int f = tid + i * 128;
        int r = f >> 5, d = (f & 31) << 1;
        float2 v = *(const float2*)(Qg + (long)(qi * 64 + r) * HSZ + d);
        *(float2*)&QP[r * 64 + (d ^ ((r & 3) << 3))] = v;
    }
    __syncthreads();

    // extract this warp's Q A-fragments (raw bits, already tf32)
    unsigned qa[8][4];
    {
        const int r = w * 16 + g;
        const int x = (r & 3) << 3;
#pragma unroll
        for (int kt = 0; kt < 8; kt++) {
            int k0 = kt * 8;
            qa[kt][0] = __float_as_uint(QP[ r      * 64 + ((k0 + tg    ) ^ x)]);
            qa[kt][1] = __float_as_uint(QP[(r + 8) * 64 + ((k0 + tg    ) ^ x)]);
            qa[kt][2] = __float_as_uint(QP[ r      * 64 + ((k0 + tg + 4) ^ x)]);
            qa[kt][3] = __float_as_uint(QP[(r + 8) * 64 + ((k0 + tg + 4) ^ x)]);
        }
    }

    float o[8][4];
#pragma unroll
    for (int nt = 0; nt < 8; nt++)
#pragma unroll
        for (int q = 0; q < 4; q++) o[nt][q] = 0.f;
    float mrow0 = -1e30f, mrow1 = -1e30f;
    float lrow0 = 0.f,    lrow1 = 0.f;
    const float SCL2E = (1.0f / 32.0f) * 1.4426950408889634f;
    const int qg0 = qi * 64 + w * 16 + g;

    for (int j = 0; j <= qi; j++) {
        if (j < qi) {
            issue_kv(j + 1, (j + 1) & 1);
            cp_commit();
            cp_wait<1>();
        } else {
            cp_wait<0>();
        }
        __syncthreads();

        const float* Kc = Ks + (j & 1) * 4096;
        const float* Vc = Vs + (j & 1) * 4096;

        // S = Q @ K^T
        float s[8][4];
#pragma unroll
        for (int nt = 0; nt < 8; nt++)
#pragma unroll
            for (int q = 0; q < 4; q++) s[nt][q] = 0.f;
#pragma unroll
        for (int kt = 0; kt < 8; kt++) {
            int k0 = kt * 8;
#pragma unroll
            for (int nt = 0; nt < 8; nt++) {
                int kp = nt * 8 + g;
                int base = kp * 64, x = (kp & 3) << 3;
                unsigned bf[2];
                bf[0] = __float_as_uint(Kc[base + ((k0 + tg    ) ^ x)]);
                bf[1] = __float_as_uint(Kc[base + ((k0 + tg + 4) ^ x)]);
                mma8(s[nt], qa[kt], bf);
            }
        }

        // causal mask (diagonal tile only)
        if (j == qi) {
#pragma unroll
            for (int nt = 0; nt < 8; nt++) {
                int kg = j * 64 + nt * 8 + 2 * tg;
                if (kg     > qg0    ) s[nt][0] = -1e30f;
                if (kg + 1 > qg0    ) s[nt][1] = -1e30f;
                if (kg     > qg0 + 8) s[nt][2] = -1e30f;
                if (kg + 1 > qg0 + 8) s[nt][3] = -1e30f;
            }
        }

        // online softmax
        float rm0 = -1e30f, rm1 = -1e30f;
#pragma unroll
        for (int nt = 0; nt < 8; nt++) {
            rm0 = fmaxf(rm0, fmaxf(s[nt][0], s[nt][1]));
            rm1 = fmaxf(rm1, fmaxf(s[nt][2], s[nt][3]));
        }
        rm0 = fmaxf(rm0, __shfl_xor_sync(0xffffffffu, rm0, 1));
        rm0 = fmaxf(rm0, __shfl_xor_sync(0xffffffffu, rm0, 2));
        rm1 = fmaxf(rm1, __shfl_xor_sync(0xffffffffu, rm1, 1));
        rm1 = fmaxf(rm1, __shfl_xor_sync(0xffffffffu, rm1, 2));

        float mn0 = fmaxf(mrow0, rm0), mn1 = fmaxf(mrow1, rm1);
        float f0 = fex2((mrow0 - mn0) * SCL2E);
        float f1 = fex2((mrow1 - mn1) * SCL2E);
        mrow0 = mn0; mrow1 = mn1;

        float sum0 = 0.f, sum1 = 0.f;
        {
            const int r = w * 16 + g;
            const int x = (r & 3) << 3;
#pragma unroll
            for (int nt = 0; nt < 8; nt++) {
                float p0 = fex2((s[nt][0] - mn0) * SCL2E);
                float p1 = fex2((s[nt][1] - mn0) * SCL2E);
                float p2 = fex2((s[nt][2] - mn1) * SCL2E);
                float p3 = fex2((s[nt][3] - mn1) * SCL2E);
                sum0 += p0 + p1;
                sum1 += p2 + p3;
                int c = nt * 8 + 2 * tg;
                // tf32-round P once at store; PV MMA reads raw bits
                *(float2*)&QP[ r      * 64 + (c ^ x)] = make_float2(rnd32(p0), rnd32(p1));
                *(float2*)&QP[(r + 8) * 64 + (c ^ x)] = make_float2(rnd32(p2), rnd32(p3));
            }
        }
        sum0 += __shfl_xor_sync(0xffffffffu, sum0, 1);
        sum0 += __shfl_xor_sync(0xffffffffu, sum0, 2);
        sum1 += __shfl_xor_sync(0xffffffffu, sum1, 1);
        sum1 += __shfl_xor_sync(0xffffffffu, sum1, 2);
        lrow0 = lrow0 * f0 + sum0;
        lrow1 = lrow1 * f1 + sum1;

#pragma unroll
        for (int nt = 0; nt < 8; nt++) {
            o[nt][0] *= f0; o[nt][1] *= f0;
            o[nt][2] *= f1; o[nt][3] *= f1;
        }
        __syncwarp();

        // O += P @ V
        {
            const int r = w * 16 + g;
            const int x = (r & 3) << 3;
#pragma unroll
            for (int kt = 0; kt < 8; kt++) {
                int k0 = kt * 8;
                unsigned pa[4];
                pa[0] = __float_as_uint(QP[ r      * 64 + ((k0 + tg    ) ^ x)]);
                pa[1] = __float_as_uint(QP[(r + 8) * 64 + ((k0 + tg    ) ^ x)]);
                pa[2] = __float_as_uint(QP[ r      * 64 + ((k0 + tg + 4) ^ x)]);
                pa[3] = __float_as_uint(QP[(r + 8) * 64 + ((k0 + tg + 4) ^ x)]);
                int kp0 = k0 + tg;
                int xv = (kp0 & 3) << 3;
#pragma unroll
                for (int nt = 0; nt < 8; nt++) {
                    int d = nt * 8 + g;
                    unsigned vb[2];
                    vb[0] = __float_as_uint(Vc[ kp0      * 64 + (d ^ xv)]);
                    vb[1] = __float_as_uint(Vc[(kp0 + 4) * 64 + (d ^ xv)]);
                    mma8(o[nt], pa, vb);
                }
            }
        }
        __syncthreads();
    }

    // finalize: divide by l, tf32-round at write (proj GEMM reads raw)
    float il0 = 1.0f / lrow0;
    float il1 = 1.0f / lrow1;
    const int b = bh >> 4, h = bh & 15;
    const int row0 = qi * 64 + w * 16 + g;
#pragma unroll
    for (int nt = 0; nt < 8; nt++) {
        int d = nt * 8 + 2 * tg;
        long idx0 = ((long)(b * TT + row0    ) * CCH) + h * HSZ + d;
        long idx1 = ((long)(b * TT + row0 + 8) * CCH) + h * HSZ + d;
        *(float2*)(g_O + idx0) =
            make_float2(rnd32(o[nt][0] * il0), rnd32(o[nt][1] * il0));
        *(float2*)(g_O + idx1) =
            make_float2(rnd32(o[nt][2] * il1), rnd32(o[nt][3] * il1));
    }
}

// ---------------------------------------------------------------------------
extern "C" void kernel_launch(void* const* d_in, const int* in_sizes, int n_in,
                              void* d_out, int out_size)
{
    (void)in_sizes; (void)n_in; (void)out_size;
    const float* X     = (const float*)d_in[0];
    const float* Wqkv  = (const float*)d_in[1];
    const float* Wproj = (const float*)d_in[2];
    float* out = (float*)d_out;

    static bool attrs_set = false;
    if (!attrs_set) {
        cudaFuncSetAttribute(gemm_tf32<0>,
            cudaFuncAttributeMaxDynamicSharedMemorySize, GEMM_SMEM);
        cudaFuncSetAttribute(gemm_tf32<1>,
            cudaFuncAttributeMaxDynamicSharedMemorySize, GEMM_SMEM);
        cudaFuncSetAttribute(attn_kernel,
            cudaFuncAttributeMaxDynamicSharedMemorySize, ATTN_SMEM);
        attrs_set = true;
    }

    // 0) round inputs to tf32 once
    round_k<0><<<(BB * TT * CCH / 4 + 255) / 256, 256>>>(X,     BB * TT * CCH);
    round_k<1><<<(CCH * 3 * CCH / 4 + 255) / 256, 256>>>(Wqkv,  CCH * 3 * CCH);
    round_k<2><<<(CCH * CCH / 4 + 255) / 256, 256>>>(Wproj, CCH * CCH);

    // 1) QKV = Xc @ Wqkvc, scattered (rounded) to g_K/g_Q/g_V [b,h,t,hs]
    gemm_tf32<0><<<dim3(3 * CCH / 128, BB * TT / 128), 256, GEMM_SMEM>>>(nullptr);

    // 2) causal flash attention -> g_O [b,t,c] (rounded)
    attn_kernel<<<dim3(TT / 64, BB * HH), 128, ATTN_SMEM>>>();

    // 3) out = g_O @ Wprojc
    gemm_tf32<1><<<dim3(CCH / 128, BB * TT / 128), 256, GEMM_SMEM>>>(out);
}

// round 10
// speedup vs baseline: 1.5555x; 1.2416x over previous
#include <cuda_runtime.h>
#include <math.h>
#include <cstdint>

#define BB  2
#define TT  2048
#define CCH 1024
#define HH  16
#define HSZ 64

// Scratch (alloc-free rule: __device__ globals).
__device__ float g_K[BB * HH * TT * HSZ];       // [b,h,t,hs]
__device__ float g_Q[BB * HH * TT * HSZ];       // [b,h,t,hs]
__device__ float g_V[BB * HH * TT * HSZ];       // [b,h,hs,t]  (TRANSPOSED)
__device__ float g_O[BB * TT * CCH];
__device__ float g_Xc[BB * TT * CCH];           // tf32-rounded X
__device__ float g_Wtqkv[3 * CCH * CCH];        // tf32-rounded W_qkv^T  [n][k]
__device__ float g_Wtproj[CCH * CCH];           // tf32-rounded W_proj^T [n][k]

// ---------------------------------------------------------------------------
// helpers
// ---------------------------------------------------------------------------
__device__ __forceinline__ unsigned f2tf32(float f) {
    unsigned u;
    asm("cvt.rna.tf32.f32 %0, %1;" : "=r"(u) : "f"(f));
    return u;
}
__device__ __forceinline__ float rnd32(float f) {
    return __uint_as_float(f2tf32(f));
}
__device__ __forceinline__ float fex2(float x) {
    float r;
    asm("ex2.approx.f32 %0, %1;" : "=f"(r) : "f"(x));
    return r;
}
__device__ __forceinline__ void mma8(float* c, const unsigned* a, const unsigned* b) {
    asm volatile(
        "mma.sync.aligned.m16n8k8.row.col.f32.tf32.tf32.f32 "
        "{%0,%1,%2,%3}, {%4,%5,%6,%7}, {%8,%9}, {%0,%1,%2,%3};\n"
        : "+f"(c[0]), "+f"(c[1]), "+f"(c[2]), "+f"(c[3])
        : "r"(a[0]), "r"(a[1]), "r"(a[2]), "r"(a[3]), "r"(b[0]), "r"(b[1]));
}
// ldmatrix x4 (b16 view of tf32 data): 4 fragment regs in one op
__device__ __forceinline__ void ldsm4(unsigned* r, uint32_t saddr) {
    asm volatile("ldmatrix.sync.aligned.m8n8.x4.shared.b16 {%0,%1,%2,%3}, [%4];"
        : "=r"(r[0]), "=r"(r[1]), "=r"(r[2]), "=r"(r[3]) : "r"(saddr));
}
__device__ __forceinline__ uint32_t smem_u32(const void* p) {
    uint32_t a;
    asm("{ .reg .u64 t; cvta.to.shared.u64 t, %1; cvt.u32.u64 %0, t; }" : "=r"(a) : "l"(p));
    return a;
}
__device__ __forceinline__ void cpa16(float* s, const float* g) {
    unsigned sa = (unsigned)__cvta_generic_to_shared(s);
    asm volatile("cp.async.cg.shared.global [%0], [%1], 16;\n" :: "r"(sa), "l"(g));
}
__device__ __forceinline__ void cpa16s(uint32_t s, const float* g) {
    asm volatile("cp.async.cg.shared.global [%0], [%1], 16;\n" :: "r"(s), "l"(g));
}
__device__ __forceinline__ void cp_commit() {
    asm volatile("cp.async.commit_group;\n");
}
template <int N>
__device__ __forceinline__ void cp_wait() {
    asm volatile("cp.async.wait_group %0;\n" :: "n"(N));
}
// byte-offset sw128 swizzle (128B rows)
__device__ __forceinline__ uint32_t swz(uint32_t o) { return o ^ ((o >> 3) & 0x70); }

// ---------------------------------------------------------------------------
// Prepass 1: round X to tf32 -> g_Xc
// ---------------------------------------------------------------------------
__global__ void round_x(const float* __restrict__ in, int n)
{
    int i = (blockIdx.x * blockDim.x + threadIdx.x) * 4;
    if (i < n) {
        float4 v = *(const float4*)(in + i);
        v.x = rnd32(v.x); v.y = rnd32(v.y);
        v.z = rnd32(v.z); v.w = rnd32(v.w);
        *(float4*)(g_Xc + i) = v;
    }
}

// ---------------------------------------------------------------------------
// Prepass 2: transpose + round W. in [R][Cc] -> out [Cc][R] (K-major rows).
// ---------------------------------------------------------------------------
template <int DST>
__global__ void transpose_rnd(const float* __restrict__ in, int R, int Cc)
{
    float* out = DST ? g_Wtproj : g_Wtqkv;
    __shared__ float ts[32][33];
    int bx = blockIdx.x * 32, by = blockIdx.y * 32;
    int tx = threadIdx.x, ty = threadIdx.y;
#pragma unroll
    for (int i = 0; i < 4; i++)
        ts[ty + i * 8][tx] = rnd32(in[(long)(by + ty + i * 8) * Cc + bx + tx]);
    __syncthreads();
#pragma unroll
    for (int i = 0; i < 4; i++)
        out[(long)(bx + ty + i * 8) * R + by + tx] = ts[tx][ty + i * 8];
}

// ---------------------------------------------------------------------------
// TF32 GEMM via mma.sync + ldmatrix: C[M,N] = A[M,K] @ Bt[N,K]^T.
// Both operands K-major in smem, 128B rows, sw128-swizzled, 2-stage cp.async.
// MODE 0: A=g_Xc, Bt=g_Wtqkv, scatter -> g_K/g_Q (rounded) + g_V transposed.
// MODE 1: A=g_O,  Bt=g_Wtproj, C=out.
// Block 256 (8 warps, 2x4), tile 128x128, BK=32.
// ---------------------------------------------------------------------------
#define GSTG_A 16384
#define GSTG   32768
#define GEMM_SMEM (2 * GSTG)

template <int MODE>
__global__ __launch_bounds__(256, 2) void gemm_lm(float* __restrict__ C)
{
    extern __shared__ float smemf[];
    const float* A  = (MODE == 0) ? g_Xc : g_O;
    const float* Bt = (MODE == 0) ? g_Wtqkv : g_Wtproj;
    const int K = CCH;
    const int N = (MODE == 0) ? 3 * CCH : CCH;

    const uint32_t sb = smem_u32(smemf);
    const int tid = threadIdx.x, lane = tid & 31, w = tid >> 5;
    const int wr = w >> 2, wc = w & 3, g = lane >> 2, tg = lane & 3;
    const int m4 = lane >> 3, ln7 = lane & 7;
    const int bm0 = blockIdx.y * 128, bn0 = blockIdx.x * 128;

    float acc[4][4][4];
#pragma unroll
    for (int mt = 0; mt < 4; mt++)
#pragma unroll
        for (int nt = 0; nt < 4; nt++)
#pragma unroll
            for (int q = 0; q < 4; q++) acc[mt][nt][q] = 0.f;

    auto issue_tile = [&](int t) {
        uint32_t base = sb + (t & 1) * GSTG;
        int kb = t * 32;
#pragma unroll
        for (int i = 0; i < 4; i++) {
            int id = tid + i * 256;
            int r = id >> 3, c = id & 7;
            cpa16s(base + swz(r * 128 + c * 16),
                   A + (long)(bm0 + r) * K + kb + c * 4);
        }
#pragma unroll
        for (int i = 0; i < 4; i++) {
            int id = tid + i * 256;
            int r = id >> 3, c = id & 7;
            cpa16s(base + GSTG_A + swz(r * 128 + c * 16),
                   Bt + (long)(bn0 + r) * K + kb + c * 4);
        }
    };

    const int nk = K / 32;
    issue_tile(0);
    cp_commit();

    for (int t = 0; t < nk; t++) {
        if (t + 1 < nk) {
            issue_tile(t + 1);
            cp_commit();
            cp_wait<1>();
        } else {
            cp_wait<0>();
        }
        __syncthreads();

        uint32_t Ab = sb + (t & 1) * GSTG;
        uint32_t Bb = Ab + GSTG_A;
#pragma unroll
        for (int ks = 0; ks < 4; ks++) {
            const int k0 = ks * 8;
            unsigned af[4][4], bf[2][4];
            const int c4A = k0 + (m4 >> 1) * 4;     // A frag col for this thread
            const int c4B = k0 + (m4 & 1) * 4;      // B frag col
#pragma unroll
            for (int mt = 0; mt < 4; mt++) {
                int rA = wr * 64 + mt * 16 + (m4 & 1) * 8 + ln7;
                ldsm4(af[mt], Ab + swz(rA * 128 + c4A * 4));
            }
#pragma unroll
            for (int ntp = 0; ntp < 2; ntp++) {
                int rB = wc * 32 + (2 * ntp + (m4 >> 1)) * 8 + ln7;
                ldsm4(bf[ntp], Bb + swz(rB * 128 + c4B * 4));
            }
#pragma unroll
            for (int mt = 0; mt < 4; mt++)
#pragma unroll
                for (int ntp = 0; ntp < 2; ntp++) {
                    mma8(acc[mt][2 * ntp],     af[mt], bf[ntp]);
                    mma8(acc[mt][2 * ntp + 1], af[mt], bf[ntp] + 2);
                }
        }
        __syncthreads();
    }

    // epilogue
#pragma unroll
    for (int mt = 0; mt < 4; mt++) {
#pragma unroll
        for (int nt = 0; nt < 4; nt++) {
            int row = bm0 + wr * 64 + mt * 16 + g;
            int col = bn0 + wc * 32 + nt * 8 + 2 * tg;
            if constexpr (MODE == 1) {
                *(float2*)(C + (long)row * N + col) =
                    make_float2(acc[mt][nt][0], acc[mt][nt][1]);
                *(float2*)(C + (long)(row + 8) * N + col) =
                    make_float2(acc[mt][nt][2], acc[mt][nt][3]);
            } else {
                int which = col >> 10;           // 0=K, 1=Q, 2=V
                int cc = col & 1023;
                int h = cc >> 6, d = cc & 63;
                int b = row >> 11, t_ = row & 2047;
                if (which == 2) {
                    // V transposed: [b,h,hs,t]
                    long base = ((long)(b * HH + h) * HSZ + d) * TT + t_;
                    g_V[base]          = rnd32(acc[mt][nt][0]);
                    g_V[base + TT]     = rnd32(acc[mt][nt][1]);
                    g_V[base + 8]      = rnd32(acc[mt][nt][2]);
                    g_V[base + TT + 8] = rnd32(acc[mt][nt][3]);
                } else {
                    float* dst = (which == 0) ? g_K : g_Q;
                    long base = ((long)(b * HH + h) * TT + t_) * HSZ + d;
                    *(float2*)(dst + base) =
                        make_float2(rnd32(acc[mt][nt][0]), rnd32(acc[mt][nt][1]));
                    *(float2*)(dst + base + 8 * HSZ) =
                        make_float2(rnd32(acc[mt][nt][2]), rnd32(acc[mt][nt][3]));
                }
            }
        }
    }
}

// ---------------------------------------------------------------------------
// Flash attention (causal) with ldmatrix fragment loads.
// Grid: (T/64, B*H). Block: 128 threads (4 warps), warp owns 16 q-rows.
// Smem tiles [64 rows][64 floats], swizzle: float c -> c ^ ((r&7)<<2).
// K tile rows = kpos; V tile rows = headdim (g_V is transposed).
// ---------------------------------------------------------------------------
#define ATTN_SMEM (5 * 64 * 64 * 4)

__global__ __launch_bounds__(128, 2) void attn_kernel()
{
    extern __shared__ float asmem[];
    float* QP = asmem;                 // 64*64
    float* Ks = asmem + 4096;          // [2][64*64]
    float* Vs = asmem + 3 * 4096;      // [2][64*64]
    const uint32_t QPb = smem_u32(QP);
    const uint32_t Ksb = smem_u32(Ks);
    const uint32_t Vsb = smem_u32(Vs);

    const int tid  = threadIdx.x;
    const int lane = tid & 31;
    const int w    = tid >> 5;
    const int g    = lane >> 2;
    const int tg   = lane & 3;
    const int m4   = lane >> 3, ln7 = lane & 7;
    const int qi   = gridDim.x - 1 - blockIdx.x;   // longest first
    const int bh   = blockIdx.y;

    const float* Qg = g_Q + (long)bh * TT * HSZ;
    const float* Kg = g_K + (long)bh * TT * HSZ;
    const float* Vg = g_V + (long)bh * TT * HSZ;   // transposed [hs][t]

    auto issue_kv = [&](int j, int st) {
#pragma unroll
        for (int i = 0; i < 8; i++) {
            int f = tid + i * 128;
            int r = f >> 4, c = (f & 15) << 2;
            int idx = st * 4096 + r * 64 + (c ^ ((r & 7) << 2));
            cpa16(Ks + idx, Kg + (long)(j * 64 + r) * HSZ + c);
            cpa16(Vs + idx, Vg + (long)r * TT + j * 64 + c);
        }
    };

    issue_kv(0, 0);
    cp_commit();

    // load Q tile (swizzled)
#pragma unroll
    for (int i = 0; i < 16; i++) {
        int f = tid + i * 128;
        int r = f >> 5, d = (f & 31) << 1;
        float2 v = *(const float2*)(Qg + (long)(qi * 64 + r) * HSZ + d);
        *(float2*)&QP[r * 64 + (d ^ ((r & 7) << 2))] = v;
    }
    __syncthreads();

    // Q A-fragments via ldmatrix (rows w*16..w*16+15)
    unsigned qa[8][4];
    {
        const int row = w * 16 + (m4 & 1) * 8 + ln7;
#pragma unroll
        for (int kt = 0; kt < 8; kt++) {
            int c4 = kt * 8 + (m4 >> 1) * 4;
            ldsm4(qa[kt], QPb + ((row * 64 + (c4 ^ ((row & 7) << 2))) << 2));
        }
    }

    float o[8][4];
#pragma unroll
    for (int nt = 0; nt < 8; nt++)
#pragma unroll
        for (int q = 0; q < 4; q++) o[nt][q] = 0.f;
    float mrow0 = -1e30f, mrow1 = -1e30f;
    float lrow0 = 0.f,    lrow1 = 0.f;
    const float SCL2E = (1.0f / 32.0f) * 1.4426950408889634f;
    const int qg0 = qi * 64 + w * 16 + g;

    for (int j = 0; j <= qi; j++) {
        if (j < qi) {
            issue_kv(j + 1, (j + 1) & 1);
            cp_commit();
            cp_wait<1>();
        } else {
            cp_wait<0>();
        }
        __syncthreads();

        const uint32_t Kb = Ksb + (j & 1) * 16384;
        const uint32_t Vb = Vsb + (j & 1) * 16384;

        // S = Q @ K^T  (ldmatrix K-frags: 2 n-tiles per x4)
        float s[8][4];
#pragma unroll
        for (int nt = 0; nt < 8; nt++)
#pragma unroll
            for (int q = 0; q < 4; q++) s[nt][q] = 0.f;
#pragma unroll
        for (int kt = 0; kt < 8; kt++) {
            int c4 = kt * 8 + (m4 & 1) * 4;
#pragma unroll
            for (int ntp = 0; ntp < 4; ntp++) {
                unsigned kb4[4];
                int row = (2 * ntp + (m4 >> 1)) * 8 + ln7;
                ldsm4(kb4, Kb + ((row * 64 + (c4 ^ ((row & 7) << 2))) << 2));
                mma8(s[2 * ntp],     qa[kt], kb4);
                mma8(s[2 * ntp + 1], qa[kt], kb4 + 2);
            }
        }

        // causal mask (diagonal tile only)
        if (j == qi) {
#pragma unroll
            for (int nt = 0; nt < 8; nt++) {
                int kg = j * 64 + nt * 8 + 2 * tg;
                if (kg     > qg0    ) s[nt][0] = -1e30f;
                if (kg + 1 > qg0    ) s[nt][1] = -1e30f;
                if (kg     > qg0 + 8) s[nt][2] = -1e30f;
                if (kg + 1 > qg0 + 8) s[nt][3] = -1e30f;
            }
        }

        // online softmax
        float rm0 = -1e30f, rm1 = -1e30f;
#pragma unroll
        for (int nt = 0; nt < 8; nt++) {
            rm0 = fmaxf(rm0, fmaxf(s[nt][0], s[nt][1]));
            rm1 = fmaxf(rm1, fmaxf(s[nt][2], s[nt][3]));
        }
        rm0 = fmaxf(rm0, __shfl_xor_sync(0xffffffffu, rm0, 1));
        rm0 = fmaxf(rm0, __shfl_xor_sync(0xffffffffu, rm0, 2));
        rm1 = fmaxf(rm1, __shfl_xor_sync(0xffffffffu, rm1, 1));
        rm1 = fmaxf(rm1, __shfl_xor_sync(0xffffffffu, rm1, 2));

        float mn0 = fmaxf(mrow0, rm0), mn1 = fmaxf(mrow1, rm1);
        float f0 = fex2((mrow0 - mn0) * SCL2E);
        float f1 = fex2((mrow1 - mn1) * SCL2E);
        mrow0 = mn0; mrow1 = mn1;

        float sum0 = 0.f, sum1 = 0.f;
        {
            const int r0 = w * 16 + g;
            const int x0 = (r0 & 7) << 2;
            const int x1 = ((r0 + 8) & 7) << 2;
#pragma unroll
            for (int nt = 0; nt < 8; nt++) {
                float p0 = fex2((s[nt][0] - mn0) * SCL2E);
                float p1 = fex2((s[nt][1] - mn0) * SCL2E);
                float p2 = fex2((s[nt][2] - mn1) * SCL2E);
                float p3 = fex2((s[nt][3] - mn1) * SCL2E);
                sum0 += p0 + p1;
                sum1 += p2 + p3;
                int c = nt * 8 + 2 * tg;
                *(float2*)&QP[ r0      * 64 + (c ^ x0)] = make_float2(rnd32(p0), rnd32(p1));
                *(float2*)&QP[(r0 + 8) * 64 + (c ^ x1)] = make_float2(rnd32(p2), rnd32(p3));
            }
        }
        sum0 += __shfl_xor_sync(0xffffffffu, sum0, 1);
        sum0 += __shfl_xor_sync(0xffffffffu, sum0, 2);
        sum1 += __shfl_xor_sync(0xffffffffu, sum1, 1);
        sum1 += __shfl_xor_sync(0xffffffffu, sum1, 2);
        lrow0 = lrow0 * f0 + sum0;
        lrow1 = lrow1 * f1 + sum1;

#pragma unroll
        for (int nt = 0; nt < 8; nt++) {
            o[nt][0] *= f0; o[nt][1] *= f0;
            o[nt][2] *= f1; o[nt][3] *= f1;
        }
        __syncwarp();

        // O += P @ V  (pa + vb via ldmatrix; V tile rows = headdim)
        {
            const int rowp = w * 16 + (m4 & 1) * 8 + ln7;
#pragma unroll
            for (int kt = 0; kt < 8; kt++) {
                int k0 = kt * 8;
                unsigned pa[4];
                int c4p = k0 + (m4 >> 1) * 4;
                ldsm4(pa, QPb + ((rowp * 64 + (c4p ^ ((rowp & 7) << 2))) << 2));
                int c4v = k0 + (m4 & 1) * 4;
#pragma unroll
                for (int ntp = 0; ntp < 4; ntp++) {
                    unsigned vb4[4];
                    int row = (2 * ntp + (m4 >> 1)) * 8 + ln7;
                    ldsm4(vb4, Vb + ((row * 64 + (c4v ^ ((row & 7) << 2))) << 2));
                    mma8(o[2 * ntp],     pa, vb4);
                    mma8(o[2 * ntp + 1], pa, vb4 + 2);
                }
            }
        }
        __syncthreads();
    }

    // finalize: divide by l, tf32-round at write (proj GEMM reads raw)
    float il0 = 1.0f / lrow0;
    float il1 = 1.0f / lrow1;
    const int b = bh >> 4, h = bh & 15;
    const int row0 = qi * 64 + w * 16 + g;
#pragma unroll
    for (int nt = 0; nt < 8; nt++) {
        int d = nt * 8 + 2 * tg;
        long idx0 = ((long)(b * TT + row0    ) * CCH) + h * HSZ + d;
        long idx1 = ((long)(b * TT + row0 + 8) * CCH) + h * HSZ + d;
        *(float2*)(g_O + idx0) =
            make_float2(rnd32(o[nt][0] * il0), rnd32(o[nt][1] * il0));
        *(float2*)(g_O + idx1) =
            make_float2(rnd32(o[nt][2] * il1), rnd32(o[nt][3] * il1));
    }
}

// ---------------------------------------------------------------------------
extern "C" void kernel_launch(void* const* d_in, const int* in_sizes, int n_in,
                              void* d_out, int out_size)
{
    (void)in_sizes; (void)n_in; (void)out_size;
    const float* X     = (const float*)d_in[0];
    const float* Wqkv  = (const float*)d_in[1];
    const float* Wproj = (const float*)d_in[2];
    float* out = (float*)d_out;

    static bool attrs_set = false;
    if (!attrs_set) {
        cudaFuncSetAttribute(gemm_lm<0>,
            cudaFuncAttributeMaxDynamicSharedMemorySize, GEMM_SMEM);
        cudaFuncSetAttribute(gemm_lm<1>,
            cudaFuncAttributeMaxDynamicSharedMemorySize, GEMM_SMEM);
        cudaFuncSetAttribute(attn_kernel,
            cudaFuncAttributeMaxDynamicSharedMemorySize, ATTN_SMEM);
        attrs_set = true;
    }

    // 0) prepass: round X; transpose+round weights into K-major
    round_x<<<(BB * TT * CCH / 4 + 255) / 256, 256>>>(X, BB * TT * CCH);
    transpose_rnd<0><<<dim3(3 * CCH / 32, CCH / 32), dim3(32, 8)>>>(Wqkv,  CCH, 3 * CCH);
    transpose_rnd<1><<<dim3(CCH / 32,     CCH / 32), dim3(32, 8)>>>(Wproj, CCH, CCH);

    // 1) QKV = Xc @ Wqkv, scattered to g_K/g_Q [b,h,t,hs] + g_V [b,h,hs,t]
    gemm_lm<0><<<dim3(3 * CCH / 128, BB * TT / 128), 256, GEMM_SMEM>>>(nullptr);

    // 2) causal flash attention -> g_O [b,t,c]
    attn_kernel<<<dim3(TT / 64, BB * HH), 128, ATTN_SMEM>>>();

    // 3) out = g_O @ Wproj
    gemm_lm<1><<<dim3(CCH / 128, BB * TT / 128), 256, GEMM_SMEM>>>(out);
}